// round 16
// baseline (speedup 1.0000x reference)
#include <cuda_runtime.h>
#include <stdint.h>

#define D_MODEL   2048
#define S_LEN     2048
#define BATCH     2
#define NUM_HEADS 16
#define HEAD_DIM  128
#define MTOT      (BATCH * S_LEN)          // 4096 rows
#define SCALE_F   0.08838834764831845f     // 1/sqrt(128)

// ---------------- scratch (device globals: no allocation allowed) ----------
__device__ float g_Q[(size_t)MTOT * D_MODEL];
__device__ float g_K[(size_t)MTOT * D_MODEL];
__device__ float g_V[(size_t)MTOT * D_MODEL];
__device__ float g_O[(size_t)MTOT * D_MODEL];
// tf32-preconverted operands
__device__ float g_Xt[(size_t)MTOT * D_MODEL];
__device__ float g_Wt[4][(size_t)D_MODEL * D_MODEL];   // q,k,v,o weights

// ---------------- helpers --------------------------------------------------
__device__ __forceinline__ uint32_t f2tf(float x) {
    uint32_t u;
    asm("cvt.rna.tf32.f32 %0, %1;" : "=r"(u) : "f"(x));
    return u;
}

__device__ __forceinline__ void mma_tf32(float c[4], const uint32_t a[4], const uint32_t b[2]) {
    asm volatile(
        "mma.sync.aligned.m16n8k8.row.col.f32.tf32.tf32.f32 "
        "{%0,%1,%2,%3}, {%4,%5,%6,%7}, {%8,%9}, {%0,%1,%2,%3};\n"
        : "+f"(c[0]), "+f"(c[1]), "+f"(c[2]), "+f"(c[3])
        : "r"(a[0]), "r"(a[1]), "r"(a[2]), "r"(a[3]),
          "r"(b[0]), "r"(b[1]));
}

__device__ __forceinline__ void cp_async16(uint32_t saddr, const float* gptr) {
    asm volatile("cp.async.cg.shared.global [%0], [%1], 16;\n"
                 :: "r"(saddr), "l"(gptr) : "memory");
}

// ---------------- tf32 pre-convert kernels ---------------------------------
__global__ __launch_bounds__(256)
void cvt_tf32_kernel(const float4* __restrict__ src, float4* __restrict__ dst) {
    int i = blockIdx.x * 256 + threadIdx.x;
    float4 v = src[i];
    uint4 o;
    o.x = f2tf(v.x); o.y = f2tf(v.y); o.z = f2tf(v.z); o.w = f2tf(v.w);
    ((uint4*)dst)[i] = o;
}

// all 4 weight matrices in one launch (blockIdx.y selects)
__global__ __launch_bounds__(256)
void cvt_w4_kernel(const float4* __restrict__ s0, const float4* __restrict__ s1,
                   const float4* __restrict__ s2, const float4* __restrict__ s3,
                   float4* __restrict__ dbase) {
    const float4* s = (blockIdx.y == 0) ? s0 : (blockIdx.y == 1) ? s1
                    : (blockIdx.y == 2) ? s2 : s3;
    float4* d = dbase + (size_t)blockIdx.y * (D_MODEL * (size_t)D_MODEL / 4);
    int i = blockIdx.x * 256 + threadIdx.x;
    float4 v = s[i];
    uint4 o;
    o.x = f2tf(v.x); o.y = f2tf(v.y); o.z = f2tf(v.z); o.w = f2tf(v.w);
    ((uint4*)d)[i] = o;
}

// ---------------- TF32 GEMM: C[M,N] = A[M,K] * W[N,K]^T + bias -------------
// CTA tile 128x128, K-tile 32, 3-stage cp.async, ONE barrier per K-tile.
// 128 threads = 4 warps in a 2x2 grid of 64x64 warp tiles:
// LDS-per-mma = 1.0 (32 LDS / 32 mma per kk) vs 1.5 for the 8-warp 32x64
// layout -> crossbar bytes per flop cut by a third. Same smem/occupancy
// envelope as the round-10 passing kernel (110592 B, 2 CTAs/SM).
#define GS 36                               // smem row stride (words)
#define STG_W (2 * 128 * GS)                // words per stage (A+B) = 9216
#define GEMM_SMEM (3 * STG_W * 4)           // 110592 B

__device__ __forceinline__
void gemm_body(const float* __restrict__ A, const float* __restrict__ W,
               const float* __restrict__ bias, float* __restrict__ C,
               bool round_out)
{
    extern __shared__ uint32_t gsm[];
    const int K = D_MODEL, N = D_MODEL;
    const int tid  = threadIdx.x;            // 0..127
    const int lane = tid & 31, warp = tid >> 5;   // 4 warps
    const int g    = lane >> 2, tig = lane & 3;
    const int wm   = warp >> 1, wn  = warp & 1;   // 2(M) x 2(N) warp grid
    const int brow = blockIdx.y * 128;
    const int bcol = blockIdx.x * 128;
    const uint32_t sbase = (uint32_t)__cvta_generic_to_shared(gsm);

    auto issue = [&](int t, int s) {
        const int kt = t * 32;
        const uint32_t so = sbase + (uint32_t)s * (STG_W * 4u);
#pragma unroll
        for (int i = 0; i < 8; i++) {            // A: 128 rows x 32 cols
            int id = tid + i * 128;
            int r  = id >> 3, c4 = (id & 7) * 4;
            cp_async16(so + (uint32_t)(r * GS + c4) * 4u,
                       A + (size_t)(brow + r) * K + kt + c4);
        }
#pragma unroll
        for (int i = 0; i < 8; i++) {            // B: 128 rows x 32 cols
            int id = tid + i * 128;
            int r  = id >> 3, c4 = (id & 7) * 4;
            cp_async16(so + (uint32_t)(128 * GS + r * GS + c4) * 4u,
                       W + (size_t)(bcol + r) * K + kt + c4);
        }
    };

    float acc[4][8][4];
#pragma unroll
    for (int mi = 0; mi < 4; mi++)
#pragma unroll
        for (int ni = 0; ni < 8; ni++)
#pragma unroll
            for (int q = 0; q < 4; q++) acc[mi][ni][q] = 0.f;

    const int nt = K / 32;   // 64
    issue(0, 0);
    asm volatile("cp.async.commit_group;" ::: "memory");
    issue(1, 1);
    asm volatile("cp.async.commit_group;" ::: "memory");

    int s = 0, snext = 2;    // stage of tile t, stage for tile t+2
#pragma unroll 1
    for (int t = 0; t < nt; t++) {
        if (t + 1 < nt) {
            asm volatile("cp.async.wait_group 1;" ::: "memory");
        } else {
            asm volatile("cp.async.wait_group 0;" ::: "memory");
        }
        __syncthreads();     // stage s ready for all; prior readers of snext done

        if (t + 2 < nt) {
            issue(t + 2, snext);
            asm volatile("cp.async.commit_group;" ::: "memory");
        }

        const uint32_t* Ac = gsm + s * STG_W;
        const uint32_t* Bc = Ac + 128 * GS;
#pragma unroll
        for (int kk = 0; kk < 32; kk += 8) {
            uint32_t a[4][4];
#pragma unroll
            for (int mi = 0; mi < 4; mi++) {
                int r0 = wm * 64 + mi * 16 + g;
                a[mi][0] = Ac[r0 * GS + kk + tig];
                a[mi][1] = Ac[(r0 + 8) * GS + kk + tig];
                a[mi][2] = Ac[r0 * GS + kk + tig + 4];
                a[mi][3] = Ac[(r0 + 8) * GS + kk + tig + 4];
            }
#pragma unroll
            for (int ni = 0; ni < 8; ni++) {
                uint32_t b[2];
                int rn = wn * 64 + ni * 8 + g;
                b[0] = Bc[rn * GS + kk + tig];
                b[1] = Bc[rn * GS + kk + tig + 4];
#pragma unroll
                for (int mi = 0; mi < 4; mi++)
                    mma_tf32(acc[mi][ni], a[mi], b);
            }
        }
        s = (s == 2) ? 0 : s + 1;
        snext = (snext == 2) ? 0 : snext + 1;
    }

    // epilogue: add bias, optional tf32 rounding (QKV outputs feed attn mma)
#pragma unroll
    for (int mi = 0; mi < 4; mi++) {
#pragma unroll
        for (int ni = 0; ni < 8; ni++) {
            int r0 = brow + wm * 64 + mi * 16 + g;
            int c0 = bcol + wn * 64 + ni * 8 + 2 * tig;
            float b0 = __ldg(bias + c0), b1 = __ldg(bias + c0 + 1);
            float v0 = acc[mi][ni][0] + b0, v1 = acc[mi][ni][1] + b1;
            float v2 = acc[mi][ni][2] + b0, v3 = acc[mi][ni][3] + b1;
            if (round_out) {
                v0 = __uint_as_float(f2tf(v0)); v1 = __uint_as_float(f2tf(v1));
                v2 = __uint_as_float(f2tf(v2)); v3 = __uint_as_float(f2tf(v3));
            }
            *(float2*)&C[(size_t)r0 * N + c0]       = make_float2(v0, v1);
            *(float2*)&C[(size_t)(r0 + 8) * N + c0] = make_float2(v2, v3);
        }
    }
}

__global__ __launch_bounds__(128, 2)
void gemm_qkv_kernel(const float* __restrict__ Xt, const float* __restrict__ Wt,
                     const float* __restrict__ bq, const float* __restrict__ bk,
                     const float* __restrict__ bv,
                     float* Qo, float* Ko, float* Vo)
{
    const float* W = Wt + (size_t)blockIdx.z * D_MODEL * D_MODEL;
    const float* b; float* C;
    if (blockIdx.z == 0)      { b = bq; C = Qo; }
    else if (blockIdx.z == 1) { b = bk; C = Ko; }
    else                      { b = bv; C = Vo; }
    gemm_body(Xt, W, b, C, true);    // round: consumed by attn mma
}

__global__ __launch_bounds__(128, 2)
void gemm_out_kernel(const float* __restrict__ A, const float* __restrict__ W,
                     const float* __restrict__ b, float* __restrict__ C)
{
    gemm_body(A, W, b, C, false);    // final output: full fp32
}

// ---------------- Flash attention (causal), TF32 mma, swizzled smem --------
// Q/K/V arrive pre-rounded to tf32 -> staging is pure uint4 copies.
// Causal load balancing: CTA processes q-tiles j and (NQ-1-j): every CTA
// does exactly 68 KV-tile units -> one balanced wave.
// (byte-identical to the round-10 passing kernel)
#define BQ 128
#define BK 32
#define NQ (S_LEN / BQ)                     // 16 q-tiles
#define ATTN_SMEM ((BQ * 128 + BK * 128 + BK * 128) * 4)   // 98304 B

__global__ __launch_bounds__(256, 2)
void attn_kernel(const float* __restrict__ Q, const float* __restrict__ K,
                 const float* __restrict__ V, float* __restrict__ O)
{
    extern __shared__ uint32_t sm[];
    uint32_t* sQ = sm;               // [128][128], swizzle col^4(row&7)
    uint32_t* sK = sQ + BQ * 128;    // [32][128],  swizzle col^4(row&7); reused as sP[128][32]
    uint32_t* sV = sK + BK * 128;    // [32][128],  swizzle col^8(row&3)

    const int tid  = threadIdx.x;
    const int lane = tid & 31, warp = tid >> 5;
    const int g    = lane >> 2, tig = lane & 3;
    const int sw   = g << 2;
    const int h = blockIdx.y, b = blockIdx.z;
    const size_t headoff = (size_t)b * S_LEN * D_MODEL + (size_t)h * HEAD_DIM;
    const int pr = warp * 16 + g;

#pragma unroll 1
    for (int seg = 0; seg < 2; seg++) {
        const int qtile = seg ? (NQ - 1 - (int)blockIdx.x) : (int)blockIdx.x;
        const int qbase = qtile * BQ;

        __syncthreads();   // prior segment's smem reads complete

        // load Q tile (128 x 128): raw bit copies, STS.128
#pragma unroll
        for (int i = 0; i < 16; i++) {
            int id = tid + i * 256;
            int r = id >> 5, c4 = (id & 31) * 4;
            uint4 q4 = *(const uint4*)(Q + headoff + (size_t)(qbase + r) * D_MODEL + c4);
            *(uint4*)&sQ[r * 128 + (c4 ^ ((r & 7) << 2))] = q4;
        }

        float oacc[16][4];
#pragma unroll
        for (int ni = 0; ni < 16; ni++)
#pragma unroll
            for (int q = 0; q < 4; q++) oacc[ni][q] = 0.f;

        float m0 = -1e30f, m1 = -1e30f, l0 = 0.f, l1 = 0.f;
        const int row0 = qbase + pr;
        const int row1 = row0 + 8;
        const int nkv  = qbase / BK + 4;

#pragma unroll 1
        for (int j = 0; j < nkv; j++) {
            const int jb = j * BK;
            __syncthreads();

            // load K,V tiles (32 x 128 each): raw uint4 copies
#pragma unroll
            for (int i = 0; i < 4; i++) {
                int id = tid + i * 256;
                int r = id >> 5, c4 = (id & 31) * 4;
                size_t go = headoff + (size_t)(jb + r) * D_MODEL + c4;
                uint4 k4 = *(const uint4*)(K + go);
                *(uint4*)&sK[r * 128 + (c4 ^ ((r & 7) << 2))] = k4;
                uint4 v4 = *(const uint4*)(V + go);
                *(uint4*)&sV[r * 128 + (c4 ^ ((r & 3) << 3))] = v4;
            }
            __syncthreads();

            // S = Q * K^T  (warp: 16 x 32)
            float sc[4][4];
#pragma unroll
            for (int ni = 0; ni < 4; ni++)
#pragma unroll
                for (int q = 0; q < 4; q++) sc[ni][q] = 0.f;

#pragma unroll
            for (int kk = 0; kk < HEAD_DIM; kk += 8) {
                uint32_t a[4];
                int r0 = warp * 16 + g;
                a[0] = sQ[r0 * 128 + ((kk + tig) ^ sw)];
                a[1] = sQ[(r0 + 8) * 128 + ((kk + tig) ^ sw)];
                a[2] = sQ[r0 * 128 + ((kk + tig + 4) ^ sw)];
                a[3] = sQ[(r0 + 8) * 128 + ((kk + tig + 4) ^ sw)];
#pragma unroll
                for (int ni = 0; ni < 4; ni++) {
                    uint32_t bb[2];
                    int rn = ni * 8 + g;
                    bb[0] = sK[rn * 128 + ((kk + tig) ^ sw)];
                    bb[1] = sK[rn * 128 + ((kk + tig + 4) ^ sw)];
                    mma_tf32(sc[ni], a, bb);
                }
            }

            // scale + causal mask + running row max
            float mx0 = m0, mx1 = m1;
#pragma unroll
            for (int ni = 0; ni < 4; ni++) {
                int c = jb + ni * 8 + 2 * tig;
                float s0 = sc[ni][0] * SCALE_F; if (c     > row0) s0 = -1e30f;
                float s1 = sc[ni][1] * SCALE_F; if (c + 1 > row0) s1 = -1e30f;
                float s2 = sc[ni][2] * SCALE_F; if (c     > row1) s2 = -1e30f;
                float s3 = sc[ni][3] * SCALE_F; if (c + 1 > row1) s3 = -1e30f;
                sc[ni][0] = s0; sc[ni][1] = s1; sc[ni][2] = s2; sc[ni][3] = s3;
                mx0 = fmaxf(mx0, fmaxf(s0, s1));
                mx1 = fmaxf(mx1, fmaxf(s2, s3));
            }
            mx0 = fmaxf(mx0, __shfl_xor_sync(0xffffffffu, mx0, 1));
            mx0 = fmaxf(mx0, __shfl_xor_sync(0xffffffffu, mx0, 2));
            mx1 = fmaxf(mx1, __shfl_xor_sync(0xffffffffu, mx1, 1));
            mx1 = fmaxf(mx1, __shfl_xor_sync(0xffffffffu, mx1, 2));

            float f0 = __expf(m0 - mx0), f1 = __expf(m1 - mx1);
            float p[4][4];
            float rs0 = 0.f, rs1 = 0.f;
#pragma unroll
            for (int ni = 0; ni < 4; ni++) {
                p[ni][0] = __expf(sc[ni][0] - mx0);
                p[ni][1] = __expf(sc[ni][1] - mx0);
                p[ni][2] = __expf(sc[ni][2] - mx1);
                p[ni][3] = __expf(sc[ni][3] - mx1);
                rs0 += p[ni][0] + p[ni][1];
                rs1 += p[ni][2] + p[ni][3];
            }
            rs0 += __shfl_xor_sync(0xffffffffu, rs0, 1);
            rs0 += __shfl_xor_sync(0xffffffffu, rs0, 2);
            rs1 += __shfl_xor_sync(0xffffffffu, rs1, 1);
            rs1 += __shfl_xor_sync(0xffffffffu, rs1, 2);

            l0 = l0 * f0 + rs0;  l1 = l1 * f1 + rs1;
            m0 = mx0;            m1 = mx1;

#pragma unroll
            for (int ni = 0; ni < 16; ni++) {
                oacc[ni][0] *= f0; oacc[ni][1] *= f0;
                oacc[ni][2] *= f1; oacc[ni][3] *= f1;
            }

            __syncthreads();   // all warps done reading sK -> safe to overlay sP

            uint32_t* sP = sK;  // [128][32], swizzle col^4(row&7); own-warp rows
#pragma unroll
            for (int ni = 0; ni < 4; ni++) {
                int c0 = ni * 8 + 2 * tig;
                *(uint2*)&sP[pr * 32 + (c0 ^ sw)] =
                    make_uint2(f2tf(p[ni][0]), f2tf(p[ni][1]));
                *(uint2*)&sP[(pr + 8) * 32 + (c0 ^ sw)] =
                    make_uint2(f2tf(p[ni][2]), f2tf(p[ni][3]));
            }
            __syncwarp();

            // O += P * V  (warp: 16 x 128)
#pragma unroll
            for (int kk = 0; kk < BK; kk += 8) {
                uint32_t a[4];
                a[0] = sP[pr * 32 + ((kk + tig) ^ sw)];
                a[1] = sP[(pr + 8) * 32 + ((kk + tig) ^ sw)];
                a[2] = sP[pr * 32 + ((kk + tig + 4) ^ sw)];
                a[3] = sP[(pr + 8) * 32 + ((kk + tig + 4) ^ sw)];
                const int sv = tig << 3;
#pragma unroll
                for (int ni = 0; ni < 16; ni++) {
                    uint32_t bb[2];
                    int cn = ni * 8 + g;
                    bb[0] = sV[(kk + tig) * 128 + (cn ^ sv)];
                    bb[1] = sV[(kk + tig + 4) * 128 + (cn ^ sv)];
                    mma_tf32(oacc[ni], a, bb);
                }
            }
        }

        // normalize + store (pre-rounded to tf32: out-proj consumes directly)
        const float inv0 = 1.f / l0, inv1 = 1.f / l1;
#pragma unroll
        for (int ni = 0; ni < 16; ni++) {
            int c = ni * 8 + 2 * tig;
            size_t o0 = headoff + (size_t)row0 * D_MODEL + c;
            size_t o1 = headoff + (size_t)row1 * D_MODEL + c;
            O[o0]     = __uint_as_float(f2tf(oacc[ni][0] * inv0));
            O[o0 + 1] = __uint_as_float(f2tf(oacc[ni][1] * inv0));
            O[o1]     = __uint_as_float(f2tf(oacc[ni][2] * inv1));
            O[o1 + 1] = __uint_as_float(f2tf(oacc[ni][3] * inv1));
        }
    }
}

// ---------------- launch ---------------------------------------------------
extern "C" void kernel_launch(void* const* d_in, const int* in_sizes, int n_in,
                              void* d_out, int out_size)
{
    const float* x  = (const float*)d_in[0];
    // d_in[1] = causal_mask (tril by construction; masking done analytically)
    const float* Wq = (const float*)d_in[2];
    const float* bq = (const float*)d_in[3];
    const float* Wk = (const float*)d_in[4];
    const float* bk = (const float*)d_in[5];
    const float* Wv = (const float*)d_in[6];
    const float* bv = (const float*)d_in[7];
    const float* Wo = (const float*)d_in[8];
    const float* bo = (const float*)d_in[9];
    float* out = (float*)d_out;

    float *q, *k, *v, *o, *xt, *wt;
    cudaGetSymbolAddress((void**)&q,  g_Q);
    cudaGetSymbolAddress((void**)&k,  g_K);
    cudaGetSymbolAddress((void**)&v,  g_V);
    cudaGetSymbolAddress((void**)&o,  g_O);
    cudaGetSymbolAddress((void**)&xt, g_Xt);
    cudaGetSymbolAddress((void**)&wt, g_Wt);

    cudaFuncSetAttribute(gemm_qkv_kernel, cudaFuncAttributeMaxDynamicSharedMemorySize, GEMM_SMEM);
    cudaFuncSetAttribute(gemm_out_kernel, cudaFuncAttributeMaxDynamicSharedMemorySize, GEMM_SMEM);
    cudaFuncSetAttribute(attn_kernel, cudaFuncAttributeMaxDynamicSharedMemorySize, ATTN_SMEM);

    const int nX4 = MTOT * D_MODEL / 4;        // 2097152
    const int nW4 = D_MODEL * D_MODEL / 4;     // 1048576

    // pre-convert operands to tf32 (rna) once
    cvt_tf32_kernel<<<nX4 / 256, 256>>>((const float4*)x, (float4*)xt);
    cvt_w4_kernel<<<dim3(nW4 / 256, 4), 256>>>(
        (const float4*)Wq, (const float4*)Wk, (const float4*)Wv, (const float4*)Wo,
        (float4*)wt);

    dim3 qkvgrid(D_MODEL / 128, MTOT / 128, 3);   // (16, 32, 3)
    gemm_qkv_kernel<<<qkvgrid, 128, GEMM_SMEM>>>(xt, wt, bq, bk, bv, q, k, v);

    attn_kernel<<<dim3(NQ / 2, NUM_HEADS, BATCH), 256, ATTN_SMEM>>>(q, k, v, o);

    dim3 ogrid(D_MODEL / 128, MTOT / 128);        // (16, 32)
    gemm_out_kernel<<<ogrid, 128, GEMM_SMEM>>>(
        o, wt + (size_t)3 * D_MODEL * D_MODEL, bo, out);
}

// round 17
// speedup vs baseline: 1.4103x; 1.4103x over previous
#include <cuda_runtime.h>
#include <stdint.h>

#define D_MODEL   2048
#define S_LEN     2048
#define BATCH     2
#define NUM_HEADS 16
#define HEAD_DIM  128
#define MTOT      (BATCH * S_LEN)          // 4096 rows
#define SCALE_F   0.08838834764831845f     // 1/sqrt(128)

// ---------------- scratch (device globals: no allocation allowed) ----------
__device__ float g_Q[(size_t)MTOT * D_MODEL];
__device__ float g_K[(size_t)MTOT * D_MODEL];
__device__ float g_V[(size_t)MTOT * D_MODEL];
__device__ float g_O[(size_t)MTOT * D_MODEL];
// tf32-preconverted operands. Slots 0-2 (Wq,Wk,Wv) and Xt are K-PERMUTED
// (within each 32-col block: dst word 4t+q holds logical col q*8+t).
// Slot 3 (Wo) is plain tf32 (consumed by the unmodified out-proj GEMM).
__device__ float g_Xt[(size_t)MTOT * D_MODEL];
__device__ float g_Wt[4][(size_t)D_MODEL * D_MODEL];

// ---------------- helpers --------------------------------------------------
__device__ __forceinline__ uint32_t f2tf(float x) {
    uint32_t u;
    asm("cvt.rna.tf32.f32 %0, %1;" : "=r"(u) : "f"(x));
    return u;
}

__device__ __forceinline__ void mma_tf32(float c[4], const uint32_t a[4], const uint32_t b[2]) {
    asm volatile(
        "mma.sync.aligned.m16n8k8.row.col.f32.tf32.tf32.f32 "
        "{%0,%1,%2,%3}, {%4,%5,%6,%7}, {%8,%9}, {%0,%1,%2,%3};\n"
        : "+f"(c[0]), "+f"(c[1]), "+f"(c[2]), "+f"(c[3])
        : "r"(a[0]), "r"(a[1]), "r"(a[2]), "r"(a[3]),
          "r"(b[0]), "r"(b[1]));
}

__device__ __forceinline__ void cp_async16(uint32_t saddr, const float* gptr) {
    asm volatile("cp.async.cg.shared.global [%0], [%1], 16;\n"
                 :: "r"(saddr), "l"(gptr) : "memory");
}

// ---------------- tf32 pre-convert kernels ---------------------------------
// Plain: round to tf32, layout unchanged (for Wo).
__global__ __launch_bounds__(256)
void cvt_tf32_kernel(const float4* __restrict__ src, float4* __restrict__ dst) {
    int i = blockIdx.x * 256 + threadIdx.x;
    float4 v = src[i];
    uint4 o;
    o.x = f2tf(v.x); o.y = f2tf(v.y); o.z = f2tf(v.z); o.w = f2tf(v.w);
    ((uint4*)dst)[i] = o;
}

// Permuting convert: within each 32-col block, dst quad at word 4t holds
// logical cols {t, t+8, t+16, t+24}. Gathered read, vectorized write.
__device__ __forceinline__
void cvt_perm_one(const float* __restrict__ src, float* __restrict__ dst, int qid) {
    int row = qid >> 9;                 // 512 quads per 2048-col row
    int blk = (qid >> 3) & 63;
    int t   = qid & 7;
    const float* sr = src + (size_t)row * D_MODEL + blk * 32 + t;
    uint4 o;
    o.x = f2tf(sr[0]);  o.y = f2tf(sr[8]);
    o.z = f2tf(sr[16]); o.w = f2tf(sr[24]);
    *(uint4*)(dst + (size_t)row * D_MODEL + blk * 32 + 4 * t) = o;
}

__global__ __launch_bounds__(256)
void cvt_x_perm_kernel(const float* __restrict__ src, float* __restrict__ dst) {
    cvt_perm_one(src, dst, blockIdx.x * 256 + threadIdx.x);
}

// q,k,v weights, permuted, one launch (blockIdx.y selects)
__global__ __launch_bounds__(256)
void cvt_w3_perm_kernel(const float* __restrict__ s0, const float* __restrict__ s1,
                        const float* __restrict__ s2, float* __restrict__ dbase) {
    const float* s = (blockIdx.y == 0) ? s0 : (blockIdx.y == 1) ? s1 : s2;
    float* d = dbase + (size_t)blockIdx.y * D_MODEL * D_MODEL;
    cvt_perm_one(s, d, blockIdx.x * 256 + threadIdx.x);
}

// ---------------- QKV GEMM (K-permuted operands, LDS.128 fragments) --------
// CTA tile 128x128, K-tile 32, 2-stage cp.async, 8 warps x 32x64 warp tiles.
// Smem rows stride 48 words (48 = 16 mod 32 -> quad loads conflict-free).
// Fragment LDS per warp-K-tile: 24 LDS.128 (vs 96 LDS.32) -> issue-bound win.
#define QGS 48                              // words per 32-word row (quad layout)
#define QSTG_W (2 * 128 * QGS)              // words per stage (A+B) = 12288
#define GEMM_Q_SMEM (2 * QSTG_W * 4)        // 98304 B -> 2 CTAs/SM

__global__ __launch_bounds__(256, 2)
void gemm_qkv_kernel(const float* __restrict__ Xt, const float* __restrict__ Wt,
                     const float* __restrict__ bq, const float* __restrict__ bk,
                     const float* __restrict__ bv,
                     float* Qo, float* Ko, float* Vo)
{
    extern __shared__ uint32_t gsm[];
    const float* W = Wt + (size_t)blockIdx.z * D_MODEL * D_MODEL;
    const float* bias; float* C;
    if (blockIdx.z == 0)      { bias = bq; C = Qo; }
    else if (blockIdx.z == 1) { bias = bk; C = Ko; }
    else                      { bias = bv; C = Vo; }

    const int K = D_MODEL, N = D_MODEL;
    const int tid  = threadIdx.x;
    const int lane = tid & 31, warp = tid >> 5;
    const int g    = lane >> 2, tig = lane & 3;
    const int wm   = warp >> 1, wn  = warp & 1;   // 4(M) x 2(N) warp grid, 32x64 tiles
    const int brow = blockIdx.y * 128;
    const int bcol = blockIdx.x * 128;
    const uint32_t sbase = (uint32_t)__cvta_generic_to_shared(gsm);

    auto issue = [&](int t) {
        const int kt = t * 32;
        const uint32_t so = sbase + (uint32_t)(t & 1) * (QSTG_W * 4u);
#pragma unroll
        for (int i = 0; i < 4; i++) {
            int id = tid + i * 256;
            int r  = id >> 3, c4 = (id & 7) * 4;
            cp_async16(so + (uint32_t)(r * QGS + c4) * 4u,
                       Xt + (size_t)(brow + r) * K + kt + c4);
            cp_async16(so + (uint32_t)(128 * QGS + r * QGS + c4) * 4u,
                       W + (size_t)(bcol + r) * K + kt + c4);
        }
        asm volatile("cp.async.commit_group;" ::: "memory");
    };

    float acc[2][8][4];
#pragma unroll
    for (int mi = 0; mi < 2; mi++)
#pragma unroll
        for (int ni = 0; ni < 8; ni++)
#pragma unroll
            for (int q = 0; q < 4; q++) acc[mi][ni][q] = 0.f;

    const int nt = K / 32;   // 64
    issue(0);

#pragma unroll 1
    for (int t = 0; t < nt; t++) {
        asm volatile("cp.async.wait_group 0;" ::: "memory");   // tile t arrived
        __syncthreads();     // visibility of t; all t-1 reads complete
        if (t + 1 < nt) issue(t + 1);

        const uint4* Aq = (const uint4*)(gsm + (t & 1) * QSTG_W);
        const uint4* Bq = Aq + 128 * (QGS / 4);   // 128 rows * 12 uint4

        // A quads: [mi][pos][q] -> fragment for kk-group q is {qa[mi][0..3][q]}
        uint32_t qa[2][4][4];
#pragma unroll
        for (int mi = 0; mi < 2; mi++) {
            int rb = (wm * 32 + mi * 16 + g) * (QGS / 4);
            *(uint4*)qa[mi][0] = Aq[rb + tig];
            *(uint4*)qa[mi][1] = Aq[rb + 8 * (QGS / 4) + tig];
            *(uint4*)qa[mi][2] = Aq[rb + tig + 4];
            *(uint4*)qa[mi][3] = Aq[rb + 8 * (QGS / 4) + tig + 4];
        }
#pragma unroll
        for (int ni = 0; ni < 8; ni++) {
            int rn = (wn * 64 + ni * 8 + g) * (QGS / 4);
            uint32_t qb0[4], qb1[4];
            *(uint4*)qb0 = Bq[rn + tig];
            *(uint4*)qb1 = Bq[rn + tig + 4];
#pragma unroll
            for (int q = 0; q < 4; q++) {       // kk groups 0,8,16,24 (in order)
                uint32_t a0[4] = {qa[0][0][q], qa[0][1][q], qa[0][2][q], qa[0][3][q]};
                uint32_t bb[2] = {qb0[q], qb1[q]};
                mma_tf32(acc[0][ni], a0, bb);
                uint32_t a1[4] = {qa[1][0][q], qa[1][1][q], qa[1][2][q], qa[1][3][q]};
                mma_tf32(acc[1][ni], a1, bb);
            }
        }
    }

    // epilogue: add bias + tf32 rounding (consumed by attn mma)
#pragma unroll
    for (int mi = 0; mi < 2; mi++) {
#pragma unroll
        for (int ni = 0; ni < 8; ni++) {
            int r0 = brow + wm * 32 + mi * 16 + g;
            int c0 = bcol + wn * 64 + ni * 8 + 2 * tig;
            float b0 = __ldg(bias + c0), b1 = __ldg(bias + c0 + 1);
            float v0 = acc[mi][ni][0] + b0, v1 = acc[mi][ni][1] + b1;
            float v2 = acc[mi][ni][2] + b0, v3 = acc[mi][ni][3] + b1;
            v0 = __uint_as_float(f2tf(v0)); v1 = __uint_as_float(f2tf(v1));
            v2 = __uint_as_float(f2tf(v2)); v3 = __uint_as_float(f2tf(v3));
            *(float2*)&C[(size_t)r0 * N + c0]       = make_float2(v0, v1);
            *(float2*)&C[(size_t)(r0 + 8) * N + c0] = make_float2(v2, v3);
        }
    }
}

// ---------------- out-proj GEMM: exact round-10 proven body -----------------
#define GS 36                               // smem row stride (words)
#define STG_W (2 * 128 * GS)                // words per stage (A+B) = 9216
#define GEMM_SMEM (3 * STG_W * 4)           // 110592 B

__global__ __launch_bounds__(256, 2)
void gemm_out_kernel(const float* __restrict__ A, const float* __restrict__ W,
                     const float* __restrict__ bias, float* __restrict__ C)
{
    extern __shared__ uint32_t gsm[];
    const int K = D_MODEL, N = D_MODEL;
    const int tid  = threadIdx.x;
    const int lane = tid & 31, warp = tid >> 5;
    const int g    = lane >> 2, tig = lane & 3;
    const int wm   = warp >> 1, wn  = warp & 1;
    const int brow = blockIdx.y * 128;
    const int bcol = blockIdx.x * 128;
    const uint32_t sbase = (uint32_t)__cvta_generic_to_shared(gsm);

    auto issue = [&](int t, int s) {
        const int kt = t * 32;
        const uint32_t so = sbase + (uint32_t)s * (STG_W * 4u);
#pragma unroll
        for (int i = 0; i < 4; i++) {
            int id = tid + i * 256;
            int r  = id >> 3, c4 = (id & 7) * 4;
            cp_async16(so + (uint32_t)(r * GS + c4) * 4u,
                       A + (size_t)(brow + r) * K + kt + c4);
            cp_async16(so + (uint32_t)(128 * GS + r * GS + c4) * 4u,
                       W + (size_t)(bcol + r) * K + kt + c4);
        }
    };

    float acc[2][8][4];
#pragma unroll
    for (int mi = 0; mi < 2; mi++)
#pragma unroll
        for (int ni = 0; ni < 8; ni++)
#pragma unroll
            for (int q = 0; q < 4; q++) acc[mi][ni][q] = 0.f;

    const int nt = K / 32;
    issue(0, 0);
    asm volatile("cp.async.commit_group;" ::: "memory");
    issue(1, 1);
    asm volatile("cp.async.commit_group;" ::: "memory");

    int s = 0, snext = 2;
#pragma unroll 1
    for (int t = 0; t < nt; t++) {
        if (t + 1 < nt) {
            asm volatile("cp.async.wait_group 1;" ::: "memory");
        } else {
            asm volatile("cp.async.wait_group 0;" ::: "memory");
        }
        __syncthreads();

        if (t + 2 < nt) {
            issue(t + 2, snext);
            asm volatile("cp.async.commit_group;" ::: "memory");
        }

        const uint32_t* Ac = gsm + s * STG_W;
        const uint32_t* Bc = Ac + 128 * GS;
#pragma unroll
        for (int kk = 0; kk < 32; kk += 8) {
            uint32_t a[2][4];
#pragma unroll
            for (int mi = 0; mi < 2; mi++) {
                int r0 = wm * 32 + mi * 16 + g;
                a[mi][0] = Ac[r0 * GS + kk + tig];
                a[mi][1] = Ac[(r0 + 8) * GS + kk + tig];
                a[mi][2] = Ac[r0 * GS + kk + tig + 4];
                a[mi][3] = Ac[(r0 + 8) * GS + kk + tig + 4];
            }
#pragma unroll
            for (int ni = 0; ni < 8; ni++) {
                uint32_t b[2];
                int rn = wn * 64 + ni * 8 + g;
                b[0] = Bc[rn * GS + kk + tig];
                b[1] = Bc[rn * GS + kk + tig + 4];
                mma_tf32(acc[0][ni], a[0], b);
                mma_tf32(acc[1][ni], a[1], b);
            }
        }
        s = (s == 2) ? 0 : s + 1;
        snext = (snext == 2) ? 0 : snext + 1;
    }

#pragma unroll
    for (int mi = 0; mi < 2; mi++) {
#pragma unroll
        for (int ni = 0; ni < 8; ni++) {
            int r0 = brow + wm * 32 + mi * 16 + g;
            int c0 = bcol + wn * 64 + ni * 8 + 2 * tig;
            float b0 = __ldg(bias + c0), b1 = __ldg(bias + c0 + 1);
            *(float2*)&C[(size_t)r0 * N + c0] =
                make_float2(acc[mi][ni][0] + b0, acc[mi][ni][1] + b1);
            *(float2*)&C[(size_t)(r0 + 8) * N + c0] =
                make_float2(acc[mi][ni][2] + b0, acc[mi][ni][3] + b1);
        }
    }
}

// ---------------- Flash attention: byte-identical to round-10 ---------------
#define BQ 128
#define BK 32
#define NQ (S_LEN / BQ)                     // 16 q-tiles
#define ATTN_SMEM ((BQ * 128 + BK * 128 + BK * 128) * 4)   // 98304 B

__global__ __launch_bounds__(256, 2)
void attn_kernel(const float* __restrict__ Q, const float* __restrict__ K,
                 const float* __restrict__ V, float* __restrict__ O)
{
    extern __shared__ uint32_t sm[];
    uint32_t* sQ = sm;               // [128][128], swizzle col^4(row&7)
    uint32_t* sK = sQ + BQ * 128;    // [32][128],  swizzle col^4(row&7); reused as sP[128][32]
    uint32_t* sV = sK + BK * 128;    // [32][128],  swizzle col^8(row&3)

    const int tid  = threadIdx.x;
    const int lane = tid & 31, warp = tid >> 5;
    const int g    = lane >> 2, tig = lane & 3;
    const int sw   = g << 2;
    const int h = blockIdx.y, b = blockIdx.z;
    const size_t headoff = (size_t)b * S_LEN * D_MODEL + (size_t)h * HEAD_DIM;
    const int pr = warp * 16 + g;

#pragma unroll 1
    for (int seg = 0; seg < 2; seg++) {
        const int qtile = seg ? (NQ - 1 - (int)blockIdx.x) : (int)blockIdx.x;
        const int qbase = qtile * BQ;

        __syncthreads();   // prior segment's smem reads complete

#pragma unroll
        for (int i = 0; i < 16; i++) {
            int id = tid + i * 256;
            int r = id >> 5, c4 = (id & 31) * 4;
            uint4 q4 = *(const uint4*)(Q + headoff + (size_t)(qbase + r) * D_MODEL + c4);
            *(uint4*)&sQ[r * 128 + (c4 ^ ((r & 7) << 2))] = q4;
        }

        float oacc[16][4];
#pragma unroll
        for (int ni = 0; ni < 16; ni++)
#pragma unroll
            for (int q = 0; q < 4; q++) oacc[ni][q] = 0.f;

        float m0 = -1e30f, m1 = -1e30f, l0 = 0.f, l1 = 0.f;
        const int row0 = qbase + pr;
        const int row1 = row0 + 8;
        const int nkv  = qbase / BK + 4;

#pragma unroll 1
        for (int j = 0; j < nkv; j++) {
            const int jb = j * BK;
            __syncthreads();

#pragma unroll
            for (int i = 0; i < 4; i++) {
                int id = tid + i * 256;
                int r = id >> 5, c4 = (id & 31) * 4;
                size_t go = headoff + (size_t)(jb + r) * D_MODEL + c4;
                uint4 k4 = *(const uint4*)(K + go);
                *(uint4*)&sK[r * 128 + (c4 ^ ((r & 7) << 2))] = k4;
                uint4 v4 = *(const uint4*)(V + go);
                *(uint4*)&sV[r * 128 + (c4 ^ ((r & 3) << 3))] = v4;
            }
            __syncthreads();

            float sc[4][4];
#pragma unroll
            for (int ni = 0; ni < 4; ni++)
#pragma unroll
                for (int q = 0; q < 4; q++) sc[ni][q] = 0.f;

#pragma unroll
            for (int kk = 0; kk < HEAD_DIM; kk += 8) {
                uint32_t a[4];
                int r0 = warp * 16 + g;
                a[0] = sQ[r0 * 128 + ((kk + tig) ^ sw)];
                a[1] = sQ[(r0 + 8) * 128 + ((kk + tig) ^ sw)];
                a[2] = sQ[r0 * 128 + ((kk + tig + 4) ^ sw)];
                a[3] = sQ[(r0 + 8) * 128 + ((kk + tig + 4) ^ sw)];
#pragma unroll
                for (int ni = 0; ni < 4; ni++) {
                    uint32_t bb[2];
                    int rn = ni * 8 + g;
                    bb[0] = sK[rn * 128 + ((kk + tig) ^ sw)];
                    bb[1] = sK[rn * 128 + ((kk + tig + 4) ^ sw)];
                    mma_tf32(sc[ni], a, bb);
                }
            }

            float mx0 = m0, mx1 = m1;
#pragma unroll
            for (int ni = 0; ni < 4; ni++) {
                int c = jb + ni * 8 + 2 * tig;
                float s0 = sc[ni][0] * SCALE_F; if (c     > row0) s0 = -1e30f;
                float s1 = sc[ni][1] * SCALE_F; if (c + 1 > row0) s1 = -1e30f;
                float s2 = sc[ni][2] * SCALE_F; if (c     > row1) s2 = -1e30f;
                float s3 = sc[ni][3] * SCALE_F; if (c + 1 > row1) s3 = -1e30f;
                sc[ni][0] = s0; sc[ni][1] = s1; sc[ni][2] = s2; sc[ni][3] = s3;
                mx0 = fmaxf(mx0, fmaxf(s0, s1));
                mx1 = fmaxf(mx1, fmaxf(s2, s3));
            }
            mx0 = fmaxf(mx0, __shfl_xor_sync(0xffffffffu, mx0, 1));
            mx0 = fmaxf(mx0, __shfl_xor_sync(0xffffffffu, mx0, 2));
            mx1 = fmaxf(mx1, __shfl_xor_sync(0xffffffffu, mx1, 1));
            mx1 = fmaxf(mx1, __shfl_xor_sync(0xffffffffu, mx1, 2));

            float f0 = __expf(m0 - mx0), f1 = __expf(m1 - mx1);
            float p[4][4];
            float rs0 = 0.f, rs1 = 0.f;
#pragma unroll
            for (int ni = 0; ni < 4; ni++) {
                p[ni][0] = __expf(sc[ni][0] - mx0);
                p[ni][1] = __expf(sc[ni][1] - mx0);
                p[ni][2] = __expf(sc[ni][2] - mx1);
                p[ni][3] = __expf(sc[ni][3] - mx1);
                rs0 += p[ni][0] + p[ni][1];
                rs1 += p[ni][2] + p[ni][3];
            }
            rs0 += __shfl_xor_sync(0xffffffffu, rs0, 1);
            rs0 += __shfl_xor_sync(0xffffffffu, rs0, 2);
            rs1 += __shfl_xor_sync(0xffffffffu, rs1, 1);
            rs1 += __shfl_xor_sync(0xffffffffu, rs1, 2);

            l0 = l0 * f0 + rs0;  l1 = l1 * f1 + rs1;
            m0 = mx0;            m1 = mx1;

#pragma unroll
            for (int ni = 0; ni < 16; ni++) {
                oacc[ni][0] *= f0; oacc[ni][1] *= f0;
                oacc[ni][2] *= f1; oacc[ni][3] *= f1;
            }

            __syncthreads();

            uint32_t* sP = sK;
#pragma unroll
            for (int ni = 0; ni < 4; ni++) {
                int c0 = ni * 8 + 2 * tig;
                *(uint2*)&sP[pr * 32 + (c0 ^ sw)] =
                    make_uint2(f2tf(p[ni][0]), f2tf(p[ni][1]));
                *(uint2*)&sP[(pr + 8) * 32 + (c0 ^ sw)] =
                    make_uint2(f2tf(p[ni][2]), f2tf(p[ni][3]));
            }
            __syncwarp();

#pragma unroll
            for (int kk = 0; kk < BK; kk += 8) {
                uint32_t a[4];
                a[0] = sP[pr * 32 + ((kk + tig) ^ sw)];
                a[1] = sP[(pr + 8) * 32 + ((kk + tig) ^ sw)];
                a[2] = sP[pr * 32 + ((kk + tig + 4) ^ sw)];
                a[3] = sP[(pr + 8) * 32 + ((kk + tig + 4) ^ sw)];
                const int sv = tig << 3;
#pragma unroll
                for (int ni = 0; ni < 16; ni++) {
                    uint32_t bb[2];
                    int cn = ni * 8 + g;
                    bb[0] = sV[(kk + tig) * 128 + (cn ^ sv)];
                    bb[1] = sV[(kk + tig + 4) * 128 + (cn ^ sv)];
                    mma_tf32(oacc[ni], a, bb);
                }
            }
        }

        const float inv0 = 1.f / l0, inv1 = 1.f / l1;
#pragma unroll
        for (int ni = 0; ni < 16; ni++) {
            int c = ni * 8 + 2 * tig;
            size_t o0 = headoff + (size_t)row0 * D_MODEL + c;
            size_t o1 = headoff + (size_t)row1 * D_MODEL + c;
            O[o0]     = __uint_as_float(f2tf(oacc[ni][0] * inv0));
            O[o0 + 1] = __uint_as_float(f2tf(oacc[ni][1] * inv0));
            O[o1]     = __uint_as_float(f2tf(oacc[ni][2] * inv1));
            O[o1 + 1] = __uint_as_float(f2tf(oacc[ni][3] * inv1));
        }
    }
}

// ---------------- launch ---------------------------------------------------
extern "C" void kernel_launch(void* const* d_in, const int* in_sizes, int n_in,
                              void* d_out, int out_size)
{
    const float* x  = (const float*)d_in[0];
    // d_in[1] = causal_mask (tril by construction; masking done analytically)
    const float* Wq = (const float*)d_in[2];
    const float* bq = (const float*)d_in[3];
    const float* Wk = (const float*)d_in[4];
    const float* bk = (const float*)d_in[5];
    const float* Wv = (const float*)d_in[6];
    const float* bv = (const float*)d_in[7];
    const float* Wo = (const float*)d_in[8];
    const float* bo = (const float*)d_in[9];
    float* out = (float*)d_out;

    float *q, *k, *v, *o, *xt, *wt;
    cudaGetSymbolAddress((void**)&q,  g_Q);
    cudaGetSymbolAddress((void**)&k,  g_K);
    cudaGetSymbolAddress((void**)&v,  g_V);
    cudaGetSymbolAddress((void**)&o,  g_O);
    cudaGetSymbolAddress((void**)&xt, g_Xt);
    cudaGetSymbolAddress((void**)&wt, g_Wt);

    cudaFuncSetAttribute(gemm_qkv_kernel, cudaFuncAttributeMaxDynamicSharedMemorySize, GEMM_Q_SMEM);
    cudaFuncSetAttribute(gemm_out_kernel, cudaFuncAttributeMaxDynamicSharedMemorySize, GEMM_SMEM);
    cudaFuncSetAttribute(attn_kernel, cudaFuncAttributeMaxDynamicSharedMemorySize, ATTN_SMEM);

    const int nXq = MTOT * D_MODEL / 8;        // 1048576 quads (8 floats per quad-gather? -> qid covers 4 floats): see below
    const int nQuadX = MTOT * D_MODEL / 4;     // 2097152 dst quads? each qid writes 4 floats
    const int nQuadW = D_MODEL * D_MODEL / 4;  // 1048576
    (void)nXq;

    // pre-convert: Xt and Wq/k/v permuted+rounded; Wo plain rounded
    cvt_x_perm_kernel<<<nQuadX / 256, 256>>>(x, xt);
    cvt_w3_perm_kernel<<<dim3(nQuadW / 256, 3), 256>>>(Wq, Wk, Wv, wt);
    cvt_tf32_kernel<<<nQuadW / 256, 256>>>(
        (const float4*)Wo, (float4*)(wt + (size_t)3 * D_MODEL * D_MODEL));

    dim3 qkvgrid(D_MODEL / 128, MTOT / 128, 3);   // (16, 32, 3)
    gemm_qkv_kernel<<<qkvgrid, 256, GEMM_Q_SMEM>>>(xt, wt, bq, bk, bv, q, k, v);

    attn_kernel<<<dim3(NQ / 2, NUM_HEADS, BATCH), 256, ATTN_SMEM>>>(q, k, v, o);

    dim3 ogrid(D_MODEL / 128, MTOT / 128);        // (16, 32)
    gemm_out_kernel<<<ogrid, 256, GEMM_SMEM>>>(
        o, wt + (size_t)3 * D_MODEL * D_MODEL, bo, out);
}